// round 5
// baseline (speedup 1.0000x reference)
#include <cuda_runtime.h>
#include <cstdint>

#define N_NODES 50000
#define E_EDGES 1600000
#define IN_DIM  128
#define OUT_DIM 64
#define SLOPE   0.1f
#define EPS     1e-12f

// Scratch (static __device__ arrays — no allocation anywhere)
__device__ float g_new[(size_t)N_NODES * OUT_DIM];   // projected features (12.8 MB)
__device__ float g_ssrc[N_NODES];                     // new[i] . a_src
__device__ float g_sdst[N_NODES];                     // new[i] . a_dst
__device__ int   g_cnt[N_NODES];                      // per-src edge counts
__device__ int   g_off[N_NODES];                      // exclusive offsets (CSR)
__device__ int   g_pos[N_NODES];                      // running fill cursor
__device__ int2  g_edge[E_EDGES];                     // (dst, bits(w)) binned by src
__device__ int   g_idx32;                             // 1 if edge_index is int32

// ---------------------------------------------------------------------------
// Edge-index fetch, dtype-dispatched on the probed flag.
// int64 layout: 2E int64 values. int32 layout: 2E int32 values.
// ---------------------------------------------------------------------------
__device__ __forceinline__ int edge_src(const void* ei, int e)
{
    if (g_idx32) return ((const int*)ei)[e];
    return (int)((const long long*)ei)[e];
}
__device__ __forceinline__ int edge_dst(const void* ei, int e)
{
    if (g_idx32) return ((const int*)ei)[E_EDGES + e];
    return (int)((const long long*)ei)[E_EDGES + e];
}

// ---------------------------------------------------------------------------
// Probe: OR the odd 32-bit words of the first 2E words of the edge buffer.
// (First 2E words are valid under BOTH dtype hypotheses.) int64 indices
// (< 2^31) have zero high halves -> flag stays 0. int32 data has src values
// in odd words -> flag becomes 1 (1.6M samples; P(all zero) ~ 0).
// ---------------------------------------------------------------------------
__global__ void probe_kernel(const unsigned* __restrict__ w)
{
    unsigned v = 0;
    for (int i = blockIdx.x * blockDim.x + threadIdx.x; i < E_EDGES;
         i += gridDim.x * blockDim.x)
        v |= w[2 * i + 1];
    if (v) g_idx32 = 1;   // benign race; zeroed by zero_kernel each call
}

// ---------------------------------------------------------------------------
// Kernel 1: new = x @ W^T + b ; fused s_src / s_dst per-node dot products.
// ---------------------------------------------------------------------------
__global__ __launch_bounds__(256, 2)
void gemm_attn_kernel(const float* __restrict__ x,
                      const float* __restrict__ W,
                      const float* __restrict__ b,
                      const float* __restrict__ a)
{
    __shared__ float Wsh[OUT_DIM * IN_DIM];   // 32 KB
    __shared__ float xs[16 * IN_DIM];          // 8 KB

    const int tid = threadIdx.x;
    const int row0 = blockIdx.x * 16;

    {
        const float4* W4 = reinterpret_cast<const float4*>(W);
        float4* Wsh4 = reinterpret_cast<float4*>(Wsh);
        #pragma unroll
        for (int i = tid; i < (OUT_DIM * IN_DIM) / 4; i += 256) Wsh4[i] = W4[i];
    }
    {
        const float4* x4 = reinterpret_cast<const float4*>(x + (size_t)row0 * IN_DIM);
        float4* xs4 = reinterpret_cast<float4*>(xs);
        #pragma unroll
        for (int i = tid; i < (16 * IN_DIM) / 4; i += 256) xs4[i] = x4[i];
    }
    __syncthreads();

    const int r  = tid >> 4;
    const int c4 = tid & 15;
    const int row = row0 + r;
    const int c   = 4 * c4;

    float acc0 = 0.f, acc1 = 0.f, acc2 = 0.f, acc3 = 0.f;
    const float4* xr = reinterpret_cast<const float4*>(xs + r * IN_DIM);
    const float4* w0 = reinterpret_cast<const float4*>(Wsh + (c + 0) * IN_DIM);
    const float4* w1 = reinterpret_cast<const float4*>(Wsh + (c + 1) * IN_DIM);
    const float4* w2 = reinterpret_cast<const float4*>(Wsh + (c + 2) * IN_DIM);
    const float4* w3 = reinterpret_cast<const float4*>(Wsh + (c + 3) * IN_DIM);

    #pragma unroll
    for (int k = 0; k < IN_DIM / 4; k++) {
        float4 xv = xr[k];
        float4 a0 = w0[k], a1 = w1[k], a2 = w2[k], a3 = w3[k];
        acc0 += xv.x * a0.x + xv.y * a0.y + xv.z * a0.z + xv.w * a0.w;
        acc1 += xv.x * a1.x + xv.y * a1.y + xv.z * a1.z + xv.w * a1.w;
        acc2 += xv.x * a2.x + xv.y * a2.y + xv.z * a2.z + xv.w * a2.w;
        acc3 += xv.x * a3.x + xv.y * a3.y + xv.z * a3.z + xv.w * a3.w;
    }

    acc0 += b[c + 0]; acc1 += b[c + 1]; acc2 += b[c + 2]; acc3 += b[c + 3];

    reinterpret_cast<float4*>(g_new)[(size_t)row * 16 + c4] =
        make_float4(acc0, acc1, acc2, acc3);

    float ps = acc0 * a[c + 0] + acc1 * a[c + 1] + acc2 * a[c + 2] + acc3 * a[c + 3];
    float pd = acc0 * a[OUT_DIM + c + 0] + acc1 * a[OUT_DIM + c + 1]
             + acc2 * a[OUT_DIM + c + 2] + acc3 * a[OUT_DIM + c + 3];

    #pragma unroll
    for (int off = 8; off > 0; off >>= 1) {
        ps += __shfl_down_sync(0xffffffffu, ps, off, 16);
        pd += __shfl_down_sync(0xffffffffu, pd, off, 16);
    }
    if (c4 == 0) {
        g_ssrc[row] = ps;
        g_sdst[row] = pd;
    }
}

// ---------------------------------------------------------------------------
// Kernel 0: zero histogram + dtype flag
// ---------------------------------------------------------------------------
__global__ void zero_kernel()
{
    int i = blockIdx.x * blockDim.x + threadIdx.x;
    if (i < N_NODES) g_cnt[i] = 0;
    if (i == 0) g_idx32 = 0;
}

// ---------------------------------------------------------------------------
// Kernel 2: histogram of src
// ---------------------------------------------------------------------------
__global__ __launch_bounds__(256)
void hist_kernel(const void* __restrict__ ei)
{
    int e = blockIdx.x * blockDim.x + threadIdx.x;
    if (e >= E_EDGES) return;
    atomicAdd(&g_cnt[edge_src(ei, e)], 1);
}

// ---------------------------------------------------------------------------
// Kernel 3: exclusive scan of g_cnt -> g_off, g_pos. Single block, 1024 thr.
// ---------------------------------------------------------------------------
#define SCAN_T 1024
#define CHUNK  ((N_NODES + SCAN_T - 1) / SCAN_T)   // 49
__global__ __launch_bounds__(SCAN_T)
void scan_kernel()
{
    __shared__ int part[SCAN_T];
    __shared__ int excl[SCAN_T];
    const int t = threadIdx.x;
    const int lo = t * CHUNK;
    const int hi = min(lo + CHUNK, N_NODES);

    int s = 0;
    for (int i = lo; i < hi; i++) s += g_cnt[i];
    part[t] = s;
    __syncthreads();

    if (t == 0) {
        int run = 0;
        for (int i = 0; i < SCAN_T; i++) { excl[i] = run; run += part[i]; }
    }
    __syncthreads();

    int run = excl[t];
    for (int i = lo; i < hi; i++) {
        g_off[i] = run;
        g_pos[i] = run;
        run += g_cnt[i];
    }
}

// ---------------------------------------------------------------------------
// Kernel 4: bin edges into CSR, computing w per edge.
// ---------------------------------------------------------------------------
__global__ __launch_bounds__(256)
void bin_kernel(const void* __restrict__ ei)
{
    int e = blockIdx.x * blockDim.x + threadIdx.x;
    if (e >= E_EDGES) return;

    int src = edge_src(ei, e);
    int dst = edge_dst(ei, e);

    float score = g_ssrc[src] + g_sdst[dst];
    float lr = score > 0.f ? score : SLOPE * score;
    float w = __expf(lr);

    int pos = atomicAdd(&g_pos[src], 1);
    g_edge[pos] = make_int2(dst, __float_as_int(w));
}

// ---------------------------------------------------------------------------
// Kernel 5: aggregate. One warp per node. Lane l owns output cols {2l, 2l+1}.
// Pure gathers from L2-resident g_new; rowsum folded into registers;
// normalized result written straight to d_out with plain stores.
// ---------------------------------------------------------------------------
__global__ __launch_bounds__(256)
void aggregate_kernel(float* __restrict__ out)
{
    const int warp = (blockIdx.x * blockDim.x + threadIdx.x) >> 5;
    const int lane = threadIdx.x & 31;
    if (warp >= N_NODES) return;

    const int beg = g_off[warp];
    const int end = beg + g_cnt[warp];

    float ax = 0.f, ay = 0.f;   // cols 2*lane, 2*lane+1
    float rsum = 0.f;

    int j = beg;
    for (; j + 4 <= end; j += 4) {
        int2 e0 = g_edge[j + 0];
        int2 e1 = g_edge[j + 1];
        int2 e2 = g_edge[j + 2];
        int2 e3 = g_edge[j + 3];
        float2 v0 = reinterpret_cast<const float2*>(g_new)[(size_t)e0.x * 32 + lane];
        float2 v1 = reinterpret_cast<const float2*>(g_new)[(size_t)e1.x * 32 + lane];
        float2 v2 = reinterpret_cast<const float2*>(g_new)[(size_t)e2.x * 32 + lane];
        float2 v3 = reinterpret_cast<const float2*>(g_new)[(size_t)e3.x * 32 + lane];
        float w0 = __int_as_float(e0.y), w1 = __int_as_float(e1.y);
        float w2 = __int_as_float(e2.y), w3 = __int_as_float(e3.y);
        ax += w0 * v0.x + w1 * v1.x + w2 * v2.x + w3 * v3.x;
        ay += w0 * v0.y + w1 * v1.y + w2 * v2.y + w3 * v3.y;
        rsum += (w0 + w1) + (w2 + w3);
    }
    for (; j < end; j++) {
        int2 e0 = g_edge[j];
        float2 v0 = reinterpret_cast<const float2*>(g_new)[(size_t)e0.x * 32 + lane];
        float w0 = __int_as_float(e0.y);
        ax += w0 * v0.x;
        ay += w0 * v0.y;
        rsum += w0;
    }

    float inv = 1.0f / (rsum + EPS);
    reinterpret_cast<float2*>(out)[(size_t)warp * 32 + lane] =
        make_float2(ax * inv, ay * inv);
}

extern "C" void kernel_launch(void* const* d_in, const int* in_sizes, int n_in,
                              void* d_out, int out_size)
{
    // Size-based dispatch (all element counts distinct) — immune to ordering.
    const float* x = 0; const void* ei = 0; const float* W = 0;
    const float* b = 0; const float* a = 0;
    for (int i = 0; i < n_in; i++) {
        switch (in_sizes[i]) {
            case N_NODES * IN_DIM:       x  = (const float*)d_in[i]; break; // 6.4M
            case 2 * E_EDGES:            ei = d_in[i];               break; // 3.2M
            case OUT_DIM * IN_DIM:       W  = (const float*)d_in[i]; break; // 8192
            case OUT_DIM:                b  = (const float*)d_in[i]; break; // 64
            case 2 * OUT_DIM:            a  = (const float*)d_in[i]; break; // 128
        }
    }
    float* out = (float*)d_out;

    zero_kernel<<<(N_NODES + 255) / 256, 256>>>();
    probe_kernel<<<1024, 256>>>((const unsigned*)ei);
    gemm_attn_kernel<<<N_NODES / 16, 256>>>(x, W, b, a);
    hist_kernel<<<(E_EDGES + 255) / 256, 256>>>(ei);
    scan_kernel<<<1, SCAN_T>>>();
    bin_kernel<<<(E_EDGES + 255) / 256, 256>>>(ei);
    aggregate_kernel<<<(N_NODES * 32 + 255) / 256, 256>>>(out);
}

// round 7
// speedup vs baseline: 2.2784x; 2.2784x over previous
#include <cuda_runtime.h>
#include <cstdint>

#define N_NODES 50000
#define E_EDGES 1600000
#define IN_DIM  128
#define OUT_DIM 64
#define SLOPE   0.1f
#define EPS     1e-12f

// Scratch (static __device__ arrays — no allocation anywhere)
__device__ float g_new[(size_t)N_NODES * OUT_DIM];   // projected features (12.8 MB)
__device__ float g_ssrc[N_NODES];                     // new[i] . a_src
__device__ float g_sdst[N_NODES];                     // new[i] . a_dst
__device__ int   g_cnt[N_NODES];                      // per-src edge counts
__device__ int   g_off[N_NODES];                      // exclusive offsets (CSR)
__device__ int   g_pos[N_NODES];                      // running fill cursor
__device__ int2  g_edge[E_EDGES];                     // (dst, bits(w)) binned by src
__device__ int   g_idx32;                             // 1 if edge_index is int32 (monotonic, deterministic)

// ---------------------------------------------------------------------------
// Probe (sampled): odd 32-bit words of the first 8192 edge slots. int64
// indices have zero high halves -> flag stays 0. int32 data puts src values
// there -> flag becomes 1. Deterministic for fixed input; monotonic flag.
// ---------------------------------------------------------------------------
__global__ void probe_kernel(const unsigned* __restrict__ w)
{
    int i = blockIdx.x * blockDim.x + threadIdx.x;   // 8192 threads
    if (w[2 * i + 1]) g_idx32 = 1;
}

// ---------------------------------------------------------------------------
// Kernel 1: new = x @ W^T + b ; fused s_src/s_dst dots; also zeroes g_cnt.
// 128 threads/block, 32 rows/block, each thread 4 rows x 4 cols.
// W transposed in smem (Wt[k][col]) -> conflict-free float4 reads.
// ---------------------------------------------------------------------------
#define GEMM_ROWS 32
__global__ __launch_bounds__(128)
void gemm_attn_kernel(const float* __restrict__ x,
                      const float* __restrict__ W,
                      const float* __restrict__ b,
                      const float* __restrict__ a)
{
    __shared__ float Wt[IN_DIM * OUT_DIM];          // 32 KB  [k][col]
    __shared__ float xs[GEMM_ROWS * IN_DIM];        // 16 KB

    const int tid  = threadIdx.x;
    const int row0 = blockIdx.x * GEMM_ROWS;

    // zero g_cnt (1563 blocks * 128 = 200064 threads >= N)
    {
        int gid = blockIdx.x * 128 + tid;
        if (gid < N_NODES) g_cnt[gid] = 0;
    }

    // Load W (64x128) transposed into Wt
    {
        const float4* W4 = reinterpret_cast<const float4*>(W);
        for (int i = tid; i < (OUT_DIM * IN_DIM) / 4; i += 128) {
            int r  = i >> 5;            // output col (W row) 0..63
            int k4 = (i & 31) * 4;      // k
            float4 v = W4[i];
            Wt[(k4 + 0) * OUT_DIM + r] = v.x;
            Wt[(k4 + 1) * OUT_DIM + r] = v.y;
            Wt[(k4 + 2) * OUT_DIM + r] = v.z;
            Wt[(k4 + 3) * OUT_DIM + r] = v.w;
        }
    }
    // Load 32 x-rows
    {
        const float4* x4 = reinterpret_cast<const float4*>(x);
        float4* xs4 = reinterpret_cast<float4*>(xs);
        for (int i = tid; i < (GEMM_ROWS * IN_DIM) / 4; i += 128) {
            int row = row0 + (i >> 5);
            if (row < N_NODES) xs4[i] = x4[(size_t)row * 32 + (i & 31)];
        }
    }
    __syncthreads();

    const int c4 = tid & 15;        // col group (4*c4 .. 4*c4+3)
    const int rp = tid >> 4;        // 0..7 -> rows 4*rp .. 4*rp+3 (local)
    const int c  = 4 * c4;

    float4 acc0 = {0,0,0,0}, acc1 = {0,0,0,0}, acc2 = {0,0,0,0}, acc3 = {0,0,0,0};
    const float* xr0 = xs + (rp * 4 + 0) * IN_DIM;
    const float* xr1 = xs + (rp * 4 + 1) * IN_DIM;
    const float* xr2 = xs + (rp * 4 + 2) * IN_DIM;
    const float* xr3 = xs + (rp * 4 + 3) * IN_DIM;

    #pragma unroll 8
    for (int k = 0; k < IN_DIM; k++) {
        float4 w4 = *reinterpret_cast<const float4*>(Wt + k * OUT_DIM + c);
        float x0 = xr0[k], x1 = xr1[k], x2 = xr2[k], x3 = xr3[k];
        acc0.x += x0 * w4.x; acc0.y += x0 * w4.y; acc0.z += x0 * w4.z; acc0.w += x0 * w4.w;
        acc1.x += x1 * w4.x; acc1.y += x1 * w4.y; acc1.z += x1 * w4.z; acc1.w += x1 * w4.w;
        acc2.x += x2 * w4.x; acc2.y += x2 * w4.y; acc2.z += x2 * w4.z; acc2.w += x2 * w4.w;
        acc3.x += x3 * w4.x; acc3.y += x3 * w4.y; acc3.z += x3 * w4.z; acc3.w += x3 * w4.w;
    }

    float4 b4 = reinterpret_cast<const float4*>(b)[c4];
    acc0.x += b4.x; acc0.y += b4.y; acc0.z += b4.z; acc0.w += b4.w;
    acc1.x += b4.x; acc1.y += b4.y; acc1.z += b4.z; acc1.w += b4.w;
    acc2.x += b4.x; acc2.y += b4.y; acc2.z += b4.z; acc2.w += b4.w;
    acc3.x += b4.x; acc3.y += b4.y; acc3.z += b4.z; acc3.w += b4.w;

    float4 as4 = reinterpret_cast<const float4*>(a)[c4];       // a_src slice
    float4 ad4 = reinterpret_cast<const float4*>(a)[16 + c4];  // a_dst slice

    float4* gn = reinterpret_cast<float4*>(g_new);
    float ps[4], pd[4];
    {
        float4 av[4] = {acc0, acc1, acc2, acc3};
        #pragma unroll
        for (int i = 0; i < 4; i++) {
            int row = row0 + rp * 4 + i;
            if (row < N_NODES) gn[(size_t)row * 16 + c4] = av[i];
            ps[i] = av[i].x * as4.x + av[i].y * as4.y + av[i].z * as4.z + av[i].w * as4.w;
            pd[i] = av[i].x * ad4.x + av[i].y * ad4.y + av[i].z * ad4.z + av[i].w * ad4.w;
        }
    }
    #pragma unroll
    for (int off = 8; off > 0; off >>= 1) {
        #pragma unroll
        for (int i = 0; i < 4; i++) {
            ps[i] += __shfl_down_sync(0xffffffffu, ps[i], off, 16);
            pd[i] += __shfl_down_sync(0xffffffffu, pd[i], off, 16);
        }
    }
    if (c4 == 0) {
        #pragma unroll
        for (int i = 0; i < 4; i++) {
            int row = row0 + rp * 4 + i;
            if (row < N_NODES) { g_ssrc[row] = ps[i]; g_sdst[row] = pd[i]; }
        }
    }
}

// ---------------------------------------------------------------------------
// Kernel 2: histogram of src, 4 edges/thread, vectorized loads
// ---------------------------------------------------------------------------
__global__ __launch_bounds__(256)
void hist_kernel(const void* __restrict__ ei)
{
    int t = blockIdx.x * blockDim.x + threadIdx.x;
    if (t >= E_EDGES / 4) return;
    int4 s4;
    if (g_idx32) {
        s4 = reinterpret_cast<const int4*>(ei)[t];
    } else {
        longlong2 p0 = reinterpret_cast<const longlong2*>(ei)[2 * t];
        longlong2 p1 = reinterpret_cast<const longlong2*>(ei)[2 * t + 1];
        s4 = make_int4((int)p0.x, (int)p0.y, (int)p1.x, (int)p1.y);
    }
    atomicAdd(&g_cnt[s4.x], 1);
    atomicAdd(&g_cnt[s4.y], 1);
    atomicAdd(&g_cnt[s4.z], 1);
    atomicAdd(&g_cnt[s4.w], 1);
}

// ---------------------------------------------------------------------------
// Kernel 3: exclusive scan of g_cnt -> g_off, g_pos. Single block 1024 thr,
// hierarchical warp shuffle scan of the per-thread partials.
// ---------------------------------------------------------------------------
#define SCAN_T 1024
#define CHUNK  ((N_NODES + SCAN_T - 1) / SCAN_T)   // 49
__global__ __launch_bounds__(SCAN_T)
void scan_kernel()
{
    __shared__ int wsum[32];
    const int t = threadIdx.x;
    const int lane = t & 31, wid = t >> 5;
    const int lo = t * CHUNK;
    const int hi = min(lo + CHUNK, N_NODES);

    int s = 0;
    for (int i = lo; i < hi; i++) s += g_cnt[i];

    // inclusive warp scan of s
    int v = s;
    #pragma unroll
    for (int off = 1; off < 32; off <<= 1) {
        int n = __shfl_up_sync(0xffffffffu, v, off);
        if (lane >= off) v += n;
    }
    if (lane == 31) wsum[wid] = v;
    __syncthreads();
    if (wid == 0) {
        int wv = (lane < 32) ? wsum[lane] : 0;
        #pragma unroll
        for (int off = 1; off < 32; off <<= 1) {
            int n = __shfl_up_sync(0xffffffffu, wv, off);
            if (lane >= off) wv += n;
        }
        wsum[lane] = wv - ((lane < 32) ? ((lane == 0) ? wv : 0) : 0); // placeholder
        // store exclusive warp base
        wsum[lane] = wv;   // inclusive; convert below
    }
    __syncthreads();
    int warp_base = (wid == 0) ? 0 : wsum[wid - 1];
    int run = warp_base + (v - s);   // exclusive prefix for this thread

    for (int i = lo; i < hi; i++) {
        g_off[i] = run;
        g_pos[i] = run;
        run += g_cnt[i];
    }
}

// ---------------------------------------------------------------------------
// Kernel 4: bin edges into CSR, computing w per edge. 4 edges/thread.
// ---------------------------------------------------------------------------
__global__ __launch_bounds__(256)
void bin_kernel(const void* __restrict__ ei)
{
    int t = blockIdx.x * blockDim.x + threadIdx.x;
    if (t >= E_EDGES / 4) return;
    int4 s4, d4;
    if (g_idx32) {
        s4 = reinterpret_cast<const int4*>(ei)[t];
        d4 = reinterpret_cast<const int4*>(ei)[E_EDGES / 4 + t];
    } else {
        longlong2 p0 = reinterpret_cast<const longlong2*>(ei)[2 * t];
        longlong2 p1 = reinterpret_cast<const longlong2*>(ei)[2 * t + 1];
        longlong2 q0 = reinterpret_cast<const longlong2*>(ei)[E_EDGES / 2 + 2 * t];
        longlong2 q1 = reinterpret_cast<const longlong2*>(ei)[E_EDGES / 2 + 2 * t + 1];
        s4 = make_int4((int)p0.x, (int)p0.y, (int)p1.x, (int)p1.y);
        d4 = make_int4((int)q0.x, (int)q0.y, (int)q1.x, (int)q1.y);
    }
    int ss[4] = {s4.x, s4.y, s4.z, s4.w};
    int dd[4] = {d4.x, d4.y, d4.z, d4.w};
    #pragma unroll
    for (int i = 0; i < 4; i++) {
        float score = g_ssrc[ss[i]] + g_sdst[dd[i]];
        float lr = score > 0.f ? score : SLOPE * score;
        float w = __expf(lr);
        int pos = atomicAdd(&g_pos[ss[i]], 1);
        g_edge[pos] = make_int2(dd[i], __float_as_int(w));
    }
}

// ---------------------------------------------------------------------------
// Kernel 5: aggregate. One warp per node; 16 lanes per edge (float4 each),
// 2 edges in flight per warp, 8 edges per unrolled iteration.
// ---------------------------------------------------------------------------
__global__ __launch_bounds__(256)
void aggregate_kernel(float* __restrict__ out)
{
    const int warp = (blockIdx.x * blockDim.x + threadIdx.x) >> 5;
    const int lane = threadIdx.x & 31;
    if (warp >= N_NODES) return;

    const int sub = lane >> 4;      // which of 2 concurrent edges
    const int sl  = lane & 15;      // float4 slot within a row

    const int beg = g_off[warp];
    const int end = beg + g_cnt[warp];

    float4 acc = {0.f, 0.f, 0.f, 0.f};
    float rsum = 0.f;
    const float4* gn = reinterpret_cast<const float4*>(g_new);

    int j = beg + sub;
    for (; j + 6 < end; j += 8) {
        int2 e0 = g_edge[j + 0];
        int2 e1 = g_edge[j + 2];
        int2 e2 = g_edge[j + 4];
        int2 e3 = g_edge[j + 6];
        float4 v0 = gn[(size_t)e0.x * 16 + sl];
        float4 v1 = gn[(size_t)e1.x * 16 + sl];
        float4 v2 = gn[(size_t)e2.x * 16 + sl];
        float4 v3 = gn[(size_t)e3.x * 16 + sl];
        float w0 = __int_as_float(e0.y), w1 = __int_as_float(e1.y);
        float w2 = __int_as_float(e2.y), w3 = __int_as_float(e3.y);
        acc.x += w0 * v0.x + w1 * v1.x + w2 * v2.x + w3 * v3.x;
        acc.y += w0 * v0.y + w1 * v1.y + w2 * v2.y + w3 * v3.y;
        acc.z += w0 * v0.z + w1 * v1.z + w2 * v2.z + w3 * v3.z;
        acc.w += w0 * v0.w + w1 * v1.w + w2 * v2.w + w3 * v3.w;
        rsum += (w0 + w1) + (w2 + w3);
    }
    for (; j < end; j += 2) {
        int2 e0 = g_edge[j];
        float4 v0 = gn[(size_t)e0.x * 16 + sl];
        float w0 = __int_as_float(e0.y);
        acc.x += w0 * v0.x; acc.y += w0 * v0.y;
        acc.z += w0 * v0.z; acc.w += w0 * v0.w;
        rsum += w0;
    }

    // combine the two edge-substreams (lanes l <-> l+16 hold same columns)
    acc.x += __shfl_xor_sync(0xffffffffu, acc.x, 16);
    acc.y += __shfl_xor_sync(0xffffffffu, acc.y, 16);
    acc.z += __shfl_xor_sync(0xffffffffu, acc.z, 16);
    acc.w += __shfl_xor_sync(0xffffffffu, acc.w, 16);
    rsum  += __shfl_xor_sync(0xffffffffu, rsum, 16);

    if (sub == 0) {
        float inv = 1.0f / (rsum + EPS);
        reinterpret_cast<float4*>(out)[(size_t)warp * 16 + sl] =
            make_float4(acc.x * inv, acc.y * inv, acc.z * inv, acc.w * inv);
    }
}

extern "C" void kernel_launch(void* const* d_in, const int* in_sizes, int n_in,
                              void* d_out, int out_size)
{
    // Size-based dispatch (all element counts distinct) — immune to ordering.
    const float* x = 0; const void* ei = 0; const float* W = 0;
    const float* b = 0; const float* a = 0;
    for (int i = 0; i < n_in; i++) {
        switch (in_sizes[i]) {
            case N_NODES * IN_DIM:       x  = (const float*)d_in[i]; break; // 6.4M
            case 2 * E_EDGES:            ei = d_in[i];               break; // 3.2M
            case OUT_DIM * IN_DIM:       W  = (const float*)d_in[i]; break; // 8192
            case OUT_DIM:                b  = (const float*)d_in[i]; break; // 64
            case 2 * OUT_DIM:            a  = (const float*)d_in[i]; break; // 128
        }
    }
    float* out = (float*)d_out;

    probe_kernel<<<32, 256>>>((const unsigned*)ei);
    gemm_attn_kernel<<<(N_NODES + GEMM_ROWS - 1) / GEMM_ROWS, 128>>>(x, W, b, a);
    hist_kernel<<<(E_EDGES / 4 + 255) / 256, 256>>>(ei);
    scan_kernel<<<1, SCAN_T>>>();
    bin_kernel<<<(E_EDGES / 4 + 255) / 256, 256>>>(ei);
    aggregate_kernel<<<(N_NODES * 32 + 255) / 256, 256>>>(out);
}

// round 12
// speedup vs baseline: 3.3106x; 1.4530x over previous
#include <cuda_runtime.h>
#include <cstdint>

#define N_NODES 50000
#define E_EDGES 1600000
#define IN_DIM  128
#define OUT_DIM 64
#define SLOPE   0.1f
#define EPS     1e-12f

// Scratch (static __device__ arrays — no allocation anywhere)
__device__ float g_new[(size_t)N_NODES * OUT_DIM];   // projected features (12.8 MB)
__device__ float g_ssrc[N_NODES];                     // new[i] . a_src
__device__ float g_sdst[N_NODES];                     // new[i] . a_dst
__device__ int   g_cnt[N_NODES];                      // per-src edge counts
__device__ int   g_off[N_NODES];                      // exclusive offsets (CSR)
__device__ int   g_pos[N_NODES];                      // running fill cursor
__device__ int2  g_edge[E_EDGES];                     // (dst, bits(w)) binned by src
__device__ int   g_idx32;                             // 1 if edge_index is int32
__device__ int   g_blk[64];                           // per-block scan partials

// ---------------------------------------------------------------------------
// Probe (sampled): odd 32-bit words of the first 8192 edge slots. int64
// indices have zero high halves -> flag stays 0; int32 src values -> 1.
// ---------------------------------------------------------------------------
__global__ void probe_kernel(const unsigned* __restrict__ w)
{
    int i = blockIdx.x * blockDim.x + threadIdx.x;   // 8192 threads
    if (w[2 * i + 1]) g_idx32 = 1;
}

// ---------------------------------------------------------------------------
// Kernel 1: new = x @ W^T + b ; fused s_src/s_dst dots; also zeroes g_cnt.
// ---------------------------------------------------------------------------
#define GEMM_ROWS 32
__global__ __launch_bounds__(128)
void gemm_attn_kernel(const float* __restrict__ x,
                      const float* __restrict__ W,
                      const float* __restrict__ b,
                      const float* __restrict__ a)
{
    __shared__ float Wt[IN_DIM * OUT_DIM];          // 32 KB  [k][col]
    __shared__ float xs[GEMM_ROWS * IN_DIM];        // 16 KB

    const int tid  = threadIdx.x;
    const int row0 = blockIdx.x * GEMM_ROWS;

    // zero g_cnt (1563 blocks * 128 = 200064 threads >= N)
    {
        int gid = blockIdx.x * 128 + tid;
        if (gid < N_NODES) g_cnt[gid] = 0;
    }

    // Load W (64x128) transposed into Wt
    {
        const float4* W4 = reinterpret_cast<const float4*>(W);
        for (int i = tid; i < (OUT_DIM * IN_DIM) / 4; i += 128) {
            int r  = i >> 5;            // output col (W row) 0..63
            int k4 = (i & 31) * 4;      // k
            float4 v = W4[i];
            Wt[(k4 + 0) * OUT_DIM + r] = v.x;
            Wt[(k4 + 1) * OUT_DIM + r] = v.y;
            Wt[(k4 + 2) * OUT_DIM + r] = v.z;
            Wt[(k4 + 3) * OUT_DIM + r] = v.w;
        }
    }
    // Load 32 x-rows
    {
        const float4* x4 = reinterpret_cast<const float4*>(x);
        float4* xs4 = reinterpret_cast<float4*>(xs);
        for (int i = tid; i < (GEMM_ROWS * IN_DIM) / 4; i += 128) {
            int row = row0 + (i >> 5);
            if (row < N_NODES) xs4[i] = x4[(size_t)row * 32 + (i & 31)];
        }
    }
    __syncthreads();

    const int c4 = tid & 15;        // col group (4*c4 .. 4*c4+3)
    const int rp = tid >> 4;        // 0..7 -> rows 4*rp .. 4*rp+3 (local)
    const int c  = 4 * c4;

    float4 acc0 = {0,0,0,0}, acc1 = {0,0,0,0}, acc2 = {0,0,0,0}, acc3 = {0,0,0,0};
    const float* xr0 = xs + (rp * 4 + 0) * IN_DIM;
    const float* xr1 = xs + (rp * 4 + 1) * IN_DIM;
    const float* xr2 = xs + (rp * 4 + 2) * IN_DIM;
    const float* xr3 = xs + (rp * 4 + 3) * IN_DIM;

    #pragma unroll 8
    for (int k = 0; k < IN_DIM; k++) {
        float4 w4 = *reinterpret_cast<const float4*>(Wt + k * OUT_DIM + c);
        float x0 = xr0[k], x1 = xr1[k], x2 = xr2[k], x3 = xr3[k];
        acc0.x += x0 * w4.x; acc0.y += x0 * w4.y; acc0.z += x0 * w4.z; acc0.w += x0 * w4.w;
        acc1.x += x1 * w4.x; acc1.y += x1 * w4.y; acc1.z += x1 * w4.z; acc1.w += x1 * w4.w;
        acc2.x += x2 * w4.x; acc2.y += x2 * w4.y; acc2.z += x2 * w4.z; acc2.w += x2 * w4.w;
        acc3.x += x3 * w4.x; acc3.y += x3 * w4.y; acc3.z += x3 * w4.z; acc3.w += x3 * w4.w;
    }

    float4 b4 = reinterpret_cast<const float4*>(b)[c4];
    acc0.x += b4.x; acc0.y += b4.y; acc0.z += b4.z; acc0.w += b4.w;
    acc1.x += b4.x; acc1.y += b4.y; acc1.z += b4.z; acc1.w += b4.w;
    acc2.x += b4.x; acc2.y += b4.y; acc2.z += b4.z; acc2.w += b4.w;
    acc3.x += b4.x; acc3.y += b4.y; acc3.z += b4.z; acc3.w += b4.w;

    float4 as4 = reinterpret_cast<const float4*>(a)[c4];       // a_src slice
    float4 ad4 = reinterpret_cast<const float4*>(a)[16 + c4];  // a_dst slice

    float4* gn = reinterpret_cast<float4*>(g_new);
    float ps[4], pd[4];
    {
        float4 av[4] = {acc0, acc1, acc2, acc3};
        #pragma unroll
        for (int i = 0; i < 4; i++) {
            int row = row0 + rp * 4 + i;
            if (row < N_NODES) gn[(size_t)row * 16 + c4] = av[i];
            ps[i] = av[i].x * as4.x + av[i].y * as4.y + av[i].z * as4.z + av[i].w * as4.w;
            pd[i] = av[i].x * ad4.x + av[i].y * ad4.y + av[i].z * ad4.z + av[i].w * ad4.w;
        }
    }
    #pragma unroll
    for (int off = 8; off > 0; off >>= 1) {
        #pragma unroll
        for (int i = 0; i < 4; i++) {
            ps[i] += __shfl_down_sync(0xffffffffu, ps[i], off, 16);
            pd[i] += __shfl_down_sync(0xffffffffu, pd[i], off, 16);
        }
    }
    if (c4 == 0) {
        #pragma unroll
        for (int i = 0; i < 4; i++) {
            int row = row0 + rp * 4 + i;
            if (row < N_NODES) { g_ssrc[row] = ps[i]; g_sdst[row] = pd[i]; }
        }
    }
}

// ---------------------------------------------------------------------------
// Kernel 2: histogram of src, 4 edges/thread, vectorized loads
// ---------------------------------------------------------------------------
__global__ __launch_bounds__(256)
void hist_kernel(const void* __restrict__ ei)
{
    int t = blockIdx.x * blockDim.x + threadIdx.x;
    if (t >= E_EDGES / 4) return;
    int4 s4;
    if (g_idx32) {
        s4 = reinterpret_cast<const int4*>(ei)[t];
    } else {
        longlong2 p0 = reinterpret_cast<const longlong2*>(ei)[2 * t];
        longlong2 p1 = reinterpret_cast<const longlong2*>(ei)[2 * t + 1];
        s4 = make_int4((int)p0.x, (int)p0.y, (int)p1.x, (int)p1.y);
    }
    atomicAdd(&g_cnt[s4.x], 1);
    atomicAdd(&g_cnt[s4.y], 1);
    atomicAdd(&g_cnt[s4.z], 1);
    atomicAdd(&g_cnt[s4.w], 1);
}

// ---------------------------------------------------------------------------
// Scan, 3-pass multi-block. 49 blocks x 256 threads x 4 items = 50176 >= N.
// ---------------------------------------------------------------------------
#define SCAN_BLOCKS 49
#define SCAN_THREADS 256
#define SCAN_ITEMS 4

// Pass 1: per-block totals
__global__ __launch_bounds__(SCAN_THREADS)
void scan_part_kernel()
{
    __shared__ int wsum[8];
    const int t = threadIdx.x;
    const int base = (blockIdx.x * SCAN_THREADS + t) * SCAN_ITEMS;

    int s = 0;
    #pragma unroll
    for (int i = 0; i < SCAN_ITEMS; i++) {
        int idx = base + i;
        if (idx < N_NODES) s += g_cnt[idx];
    }
    // warp reduce
    #pragma unroll
    for (int off = 16; off > 0; off >>= 1) s += __shfl_down_sync(0xffffffffu, s, off);
    if ((t & 31) == 0) wsum[t >> 5] = s;
    __syncthreads();
    if (t == 0) {
        int tot = 0;
        #pragma unroll
        for (int i = 0; i < 8; i++) tot += wsum[i];
        g_blk[blockIdx.x] = tot;
    }
}

// Pass 2: exclusive scan of 49 block totals (tiny, one warp's worth of work)
__global__ void scan_top_kernel()
{
    if (threadIdx.x == 0) {
        int run = 0;
        for (int i = 0; i < SCAN_BLOCKS; i++) {
            int v = g_blk[i];
            g_blk[i] = run;
            run += v;
        }
    }
}

// Pass 3: write exclusive offsets
__global__ __launch_bounds__(SCAN_THREADS)
void scan_write_kernel()
{
    __shared__ int wbase[8];
    const int t = threadIdx.x;
    const int lane = t & 31, wid = t >> 5;
    const int base = (blockIdx.x * SCAN_THREADS + t) * SCAN_ITEMS;

    int c[SCAN_ITEMS];
    int s = 0;
    #pragma unroll
    for (int i = 0; i < SCAN_ITEMS; i++) {
        int idx = base + i;
        c[i] = (idx < N_NODES) ? g_cnt[idx] : 0;
        s += c[i];
    }
    // inclusive warp scan of s
    int v = s;
    #pragma unroll
    for (int off = 1; off < 32; off <<= 1) {
        int n = __shfl_up_sync(0xffffffffu, v, off);
        if (lane >= off) v += n;
    }
    if (lane == 31) wbase[wid] = v;
    __syncthreads();
    if (t == 0) {
        int run = 0;
        #pragma unroll
        for (int i = 0; i < 8; i++) { int w = wbase[i]; wbase[i] = run; run += w; }
    }
    __syncthreads();

    int run = g_blk[blockIdx.x] + wbase[wid] + (v - s);   // exclusive prefix
    #pragma unroll
    for (int i = 0; i < SCAN_ITEMS; i++) {
        int idx = base + i;
        if (idx < N_NODES) {
            g_off[idx] = run;
            g_pos[idx] = run;
            run += c[i];
        }
    }
}

// ---------------------------------------------------------------------------
// Kernel 4: bin edges into CSR, computing w per edge. 4 edges/thread.
// ---------------------------------------------------------------------------
__global__ __launch_bounds__(256)
void bin_kernel(const void* __restrict__ ei)
{
    int t = blockIdx.x * blockDim.x + threadIdx.x;
    if (t >= E_EDGES / 4) return;
    int4 s4, d4;
    if (g_idx32) {
        s4 = reinterpret_cast<const int4*>(ei)[t];
        d4 = reinterpret_cast<const int4*>(ei)[E_EDGES / 4 + t];
    } else {
        longlong2 p0 = reinterpret_cast<const longlong2*>(ei)[2 * t];
        longlong2 p1 = reinterpret_cast<const longlong2*>(ei)[2 * t + 1];
        longlong2 q0 = reinterpret_cast<const longlong2*>(ei)[E_EDGES / 2 + 2 * t];
        longlong2 q1 = reinterpret_cast<const longlong2*>(ei)[E_EDGES / 2 + 2 * t + 1];
        s4 = make_int4((int)p0.x, (int)p0.y, (int)p1.x, (int)p1.y);
        d4 = make_int4((int)q0.x, (int)q0.y, (int)q1.x, (int)q1.y);
    }
    int ss[4] = {s4.x, s4.y, s4.z, s4.w};
    int dd[4] = {d4.x, d4.y, d4.z, d4.w};
    #pragma unroll
    for (int i = 0; i < 4; i++) {
        float score = g_ssrc[ss[i]] + g_sdst[dd[i]];
        float lr = score > 0.f ? score : SLOPE * score;
        float w = __expf(lr);
        int pos = atomicAdd(&g_pos[ss[i]], 1);
        g_edge[pos] = make_int2(dd[i], __float_as_int(w));
    }
}

// ---------------------------------------------------------------------------
// Kernel 5: aggregate. One warp per node; 16 lanes per edge (float4 each),
// 2 edges in flight per warp, 8 edges per unrolled iteration.
// ---------------------------------------------------------------------------
__global__ __launch_bounds__(256)
void aggregate_kernel(float* __restrict__ out)
{
    const int warp = (blockIdx.x * blockDim.x + threadIdx.x) >> 5;
    const int lane = threadIdx.x & 31;
    if (warp >= N_NODES) return;

    const int sub = lane >> 4;      // which of 2 concurrent edges
    const int sl  = lane & 15;      // float4 slot within a row

    const int beg = g_off[warp];
    const int end = beg + g_cnt[warp];

    float4 acc = {0.f, 0.f, 0.f, 0.f};
    float rsum = 0.f;
    const float4* gn = reinterpret_cast<const float4*>(g_new);

    int j = beg + sub;
    for (; j + 6 < end; j += 8) {
        int2 e0 = g_edge[j + 0];
        int2 e1 = g_edge[j + 2];
        int2 e2 = g_edge[j + 4];
        int2 e3 = g_edge[j + 6];
        float4 v0 = gn[(size_t)e0.x * 16 + sl];
        float4 v1 = gn[(size_t)e1.x * 16 + sl];
        float4 v2 = gn[(size_t)e2.x * 16 + sl];
        float4 v3 = gn[(size_t)e3.x * 16 + sl];
        float w0 = __int_as_float(e0.y), w1 = __int_as_float(e1.y);
        float w2 = __int_as_float(e2.y), w3 = __int_as_float(e3.y);
        acc.x += w0 * v0.x + w1 * v1.x + w2 * v2.x + w3 * v3.x;
        acc.y += w0 * v0.y + w1 * v1.y + w2 * v2.y + w3 * v3.y;
        acc.z += w0 * v0.z + w1 * v1.z + w2 * v2.z + w3 * v3.z;
        acc.w += w0 * v0.w + w1 * v1.w + w2 * v2.w + w3 * v3.w;
        rsum += (w0 + w1) + (w2 + w3);
    }
    for (; j < end; j += 2) {
        int2 e0 = g_edge[j];
        float4 v0 = gn[(size_t)e0.x * 16 + sl];
        float w0 = __int_as_float(e0.y);
        acc.x += w0 * v0.x; acc.y += w0 * v0.y;
        acc.z += w0 * v0.z; acc.w += w0 * v0.w;
        rsum += w0;
    }

    // combine the two edge-substreams (lanes l <-> l+16 hold same columns)
    acc.x += __shfl_xor_sync(0xffffffffu, acc.x, 16);
    acc.y += __shfl_xor_sync(0xffffffffu, acc.y, 16);
    acc.z += __shfl_xor_sync(0xffffffffu, acc.z, 16);
    acc.w += __shfl_xor_sync(0xffffffffu, acc.w, 16);
    rsum  += __shfl_xor_sync(0xffffffffu, rsum, 16);

    if (sub == 0) {
        float inv = 1.0f / (rsum + EPS);
        reinterpret_cast<float4*>(out)[(size_t)warp * 16 + sl] =
            make_float4(acc.x * inv, acc.y * inv, acc.z * inv, acc.w * inv);
    }
}

extern "C" void kernel_launch(void* const* d_in, const int* in_sizes, int n_in,
                              void* d_out, int out_size)
{
    // Size-based dispatch (all element counts distinct) — immune to ordering.
    const float* x = 0; const void* ei = 0; const float* W = 0;
    const float* b = 0; const float* a = 0;
    for (int i = 0; i < n_in; i++) {
        switch (in_sizes[i]) {
            case N_NODES * IN_DIM:       x  = (const float*)d_in[i]; break; // 6.4M
            case 2 * E_EDGES:            ei = d_in[i];               break; // 3.2M
            case OUT_DIM * IN_DIM:       W  = (const float*)d_in[i]; break; // 8192
            case OUT_DIM:                b  = (const float*)d_in[i]; break; // 64
            case 2 * OUT_DIM:            a  = (const float*)d_in[i]; break; // 128
        }
    }
    float* out = (float*)d_out;

    probe_kernel<<<32, 256>>>((const unsigned*)ei);
    gemm_attn_kernel<<<(N_NODES + GEMM_ROWS - 1) / GEMM_ROWS, 128>>>(x, W, b, a);
    hist_kernel<<<(E_EDGES / 4 + 255) / 256, 256>>>(ei);
    scan_part_kernel<<<SCAN_BLOCKS, SCAN_THREADS>>>();
    scan_top_kernel<<<1, 32>>>();
    scan_write_kernel<<<SCAN_BLOCKS, SCAN_THREADS>>>();
    bin_kernel<<<(E_EDGES / 4 + 255) / 256, 256>>>(ei);
    aggregate_kernel<<<(N_NODES * 32 + 255) / 256, 256>>>(out);
}

// round 13
// speedup vs baseline: 3.5253x; 1.0648x over previous
#include <cuda_runtime.h>
#include <cstdint>

#define N_NODES 50000
#define E_EDGES 1600000
#define IN_DIM  128
#define OUT_DIM 64
#define SLOPE   0.1f
#define EPS     1e-12f

// Scratch (static __device__ arrays — no allocation anywhere)
__device__ float g_new[(size_t)N_NODES * OUT_DIM];   // projected features (12.8 MB)
__device__ float g_ssrc[N_NODES];                     // new[i] . a_src
__device__ float g_sdst[N_NODES];                     // new[i] . a_dst
__device__ int   g_cnt[N_NODES];                      // per-src edge counts
__device__ int   g_off[N_NODES];                      // exclusive offsets (CSR)
__device__ int   g_pos[N_NODES];                      // running fill cursor
__device__ int2  g_edge[E_EDGES];                     // (dst, bits(w)) binned by src
__device__ int   g_idx32;                             // 1 if edge_index is int32
__device__ int   g_blk[64];                           // per-block scan partials

// ---- packed f32x2 helpers (Blackwell; FFMA2 only reachable via PTX) --------
__device__ __forceinline__ void fma2(unsigned long long& acc,
                                     unsigned long long a, unsigned long long b)
{
    asm("fma.rn.f32x2 %0, %1, %2, %0;" : "+l"(acc) : "l"(a), "l"(b));
}
__device__ __forceinline__ unsigned long long pack2(float lo, float hi)
{
    unsigned long long r;
    asm("mov.b64 %0, {%1, %2};" : "=l"(r) : "f"(lo), "f"(hi));
    return r;
}
__device__ __forceinline__ float2 unpack2(unsigned long long v)
{
    float2 r;
    asm("mov.b64 {%0, %1}, %2;" : "=f"(r.x), "=f"(r.y) : "l"(v));
    return r;
}

// ---------------------------------------------------------------------------
// Kernel 0: zero g_cnt + dtype probe (sampled odd words of first 8192 slots).
// ---------------------------------------------------------------------------
__global__ void probe_zero_kernel(const unsigned* __restrict__ w)
{
    int i = blockIdx.x * blockDim.x + threadIdx.x;
    if (i < N_NODES) g_cnt[i] = 0;
    if (i < 8192 && w[2 * i + 1]) g_idx32 = 1;   // monotonic, deterministic
}

// ---------------------------------------------------------------------------
// Kernel 1: new = x @ W^T + b ; fused s_src/s_dst dots; fused src histogram.
// 128 threads/block, 32 rows/block, each thread 4 rows x 4 cols, FFMA2 math.
// ---------------------------------------------------------------------------
#define GEMM_ROWS 32
__global__ __launch_bounds__(128)
void gemm_attn_hist_kernel(const float* __restrict__ x,
                           const float* __restrict__ W,
                           const float* __restrict__ b,
                           const float* __restrict__ a,
                           const void* __restrict__ ei)
{
    __shared__ float Wt[IN_DIM * OUT_DIM];          // 32 KB  [k][col]
    __shared__ float xs[GEMM_ROWS * IN_DIM];        // 16 KB

    const int tid  = threadIdx.x;
    const int row0 = blockIdx.x * GEMM_ROWS;

    // Load W (64x128) transposed into Wt
    {
        const float4* W4 = reinterpret_cast<const float4*>(W);
        for (int i = tid; i < (OUT_DIM * IN_DIM) / 4; i += 128) {
            int r  = i >> 5;            // output col (W row) 0..63
            int k4 = (i & 31) * 4;      // k
            float4 v = W4[i];
            Wt[(k4 + 0) * OUT_DIM + r] = v.x;
            Wt[(k4 + 1) * OUT_DIM + r] = v.y;
            Wt[(k4 + 2) * OUT_DIM + r] = v.z;
            Wt[(k4 + 3) * OUT_DIM + r] = v.w;
        }
    }
    // Load 32 x-rows
    {
        const float4* x4 = reinterpret_cast<const float4*>(x);
        float4* xs4 = reinterpret_cast<float4*>(xs);
        for (int i = tid; i < (GEMM_ROWS * IN_DIM) / 4; i += 128) {
            int row = row0 + (i >> 5);
            if (row < N_NODES) xs4[i] = x4[(size_t)row * 32 + (i & 31)];
        }
    }
    __syncthreads();

    const int c4 = tid & 15;        // col group (4*c4 .. 4*c4+3)
    const int rp = tid >> 4;        // 0..7 -> rows 4*rp .. 4*rp+3 (local)
    const int c  = 4 * c4;

    // accumulators: [row][col-pair], each u64 = 2 packed floats
    unsigned long long alo[4] = {0, 0, 0, 0};   // cols c, c+1
    unsigned long long ahi[4] = {0, 0, 0, 0};   // cols c+2, c+3
    const float* xr0 = xs + (rp * 4 + 0) * IN_DIM;
    const float* xr1 = xs + (rp * 4 + 1) * IN_DIM;
    const float* xr2 = xs + (rp * 4 + 2) * IN_DIM;
    const float* xr3 = xs + (rp * 4 + 3) * IN_DIM;

    #pragma unroll 8
    for (int k = 0; k < IN_DIM; k++) {
        ulonglong2 wv = *reinterpret_cast<const ulonglong2*>(Wt + k * OUT_DIM + c);
        unsigned long long x0 = pack2(xr0[k], xr0[k]);
        unsigned long long x1 = pack2(xr1[k], xr1[k]);
        unsigned long long x2 = pack2(xr2[k], xr2[k]);
        unsigned long long x3 = pack2(xr3[k], xr3[k]);
        fma2(alo[0], x0, wv.x); fma2(ahi[0], x0, wv.y);
        fma2(alo[1], x1, wv.x); fma2(ahi[1], x1, wv.y);
        fma2(alo[2], x2, wv.x); fma2(ahi[2], x2, wv.y);
        fma2(alo[3], x3, wv.x); fma2(ahi[3], x3, wv.y);
    }

    float4 b4  = reinterpret_cast<const float4*>(b)[c4];
    float4 as4 = reinterpret_cast<const float4*>(a)[c4];       // a_src slice
    float4 ad4 = reinterpret_cast<const float4*>(a)[16 + c4];  // a_dst slice

    float4* gn = reinterpret_cast<float4*>(g_new);
    float ps[4], pd[4];
    #pragma unroll
    for (int i = 0; i < 4; i++) {
        float2 lo = unpack2(alo[i]);
        float2 hi = unpack2(ahi[i]);
        float4 av = make_float4(lo.x + b4.x, lo.y + b4.y, hi.x + b4.z, hi.y + b4.w);
        int row = row0 + rp * 4 + i;
        if (row < N_NODES) gn[(size_t)row * 16 + c4] = av;
        ps[i] = av.x * as4.x + av.y * as4.y + av.z * as4.z + av.w * as4.w;
        pd[i] = av.x * ad4.x + av.y * ad4.y + av.z * ad4.z + av.w * ad4.w;
    }
    #pragma unroll
    for (int off = 8; off > 0; off >>= 1) {
        #pragma unroll
        for (int i = 0; i < 4; i++) {
            ps[i] += __shfl_down_sync(0xffffffffu, ps[i], off, 16);
            pd[i] += __shfl_down_sync(0xffffffffu, pd[i], off, 16);
        }
    }
    if (c4 == 0) {
        #pragma unroll
        for (int i = 0; i < 4; i++) {
            int row = row0 + rp * 4 + i;
            if (row < N_NODES) { g_ssrc[row] = ps[i]; g_sdst[row] = pd[i]; }
        }
    }

    // ---- fused histogram tail: overlaps atomic/load latency with other
    //      warps' FMA streams. g_cnt zeroed by probe_zero_kernel (prior launch).
    {
        const int nt = gridDim.x * 128;
        for (int t = blockIdx.x * 128 + tid; t < E_EDGES / 4; t += nt) {
            int4 s4;
            if (g_idx32) {
                s4 = reinterpret_cast<const int4*>(ei)[t];
            } else {
                longlong2 p0 = reinterpret_cast<const longlong2*>(ei)[2 * t];
                longlong2 p1 = reinterpret_cast<const longlong2*>(ei)[2 * t + 1];
                s4 = make_int4((int)p0.x, (int)p0.y, (int)p1.x, (int)p1.y);
            }
            atomicAdd(&g_cnt[s4.x], 1);
            atomicAdd(&g_cnt[s4.y], 1);
            atomicAdd(&g_cnt[s4.z], 1);
            atomicAdd(&g_cnt[s4.w], 1);
        }
    }
}

// ---------------------------------------------------------------------------
// Scan, 3-pass multi-block. 49 blocks x 256 threads x 4 items = 50176 >= N.
// ---------------------------------------------------------------------------
#define SCAN_BLOCKS 49
#define SCAN_THREADS 256
#define SCAN_ITEMS 4

__global__ __launch_bounds__(SCAN_THREADS)
void scan_part_kernel()
{
    __shared__ int wsum[8];
    const int t = threadIdx.x;
    const int base = (blockIdx.x * SCAN_THREADS + t) * SCAN_ITEMS;

    int s = 0;
    #pragma unroll
    for (int i = 0; i < SCAN_ITEMS; i++) {
        int idx = base + i;
        if (idx < N_NODES) s += g_cnt[idx];
    }
    #pragma unroll
    for (int off = 16; off > 0; off >>= 1) s += __shfl_down_sync(0xffffffffu, s, off);
    if ((t & 31) == 0) wsum[t >> 5] = s;
    __syncthreads();
    if (t == 0) {
        int tot = 0;
        #pragma unroll
        for (int i = 0; i < 8; i++) tot += wsum[i];
        g_blk[blockIdx.x] = tot;
    }
}

__global__ void scan_top_kernel()
{
    if (threadIdx.x == 0) {
        int run = 0;
        for (int i = 0; i < SCAN_BLOCKS; i++) {
            int v = g_blk[i];
            g_blk[i] = run;
            run += v;
        }
    }
}

__global__ __launch_bounds__(SCAN_THREADS)
void scan_write_kernel()
{
    __shared__ int wbase[8];
    const int t = threadIdx.x;
    const int lane = t & 31, wid = t >> 5;
    const int base = (blockIdx.x * SCAN_THREADS + t) * SCAN_ITEMS;

    int c[SCAN_ITEMS];
    int s = 0;
    #pragma unroll
    for (int i = 0; i < SCAN_ITEMS; i++) {
        int idx = base + i;
        c[i] = (idx < N_NODES) ? g_cnt[idx] : 0;
        s += c[i];
    }
    int v = s;
    #pragma unroll
    for (int off = 1; off < 32; off <<= 1) {
        int n = __shfl_up_sync(0xffffffffu, v, off);
        if (lane >= off) v += n;
    }
    if (lane == 31) wbase[wid] = v;
    __syncthreads();
    if (t == 0) {
        int run = 0;
        #pragma unroll
        for (int i = 0; i < 8; i++) { int w = wbase[i]; wbase[i] = run; run += w; }
    }
    __syncthreads();

    int run = g_blk[blockIdx.x] + wbase[wid] + (v - s);   // exclusive prefix
    #pragma unroll
    for (int i = 0; i < SCAN_ITEMS; i++) {
        int idx = base + i;
        if (idx < N_NODES) {
            g_off[idx] = run;
            g_pos[idx] = run;
            run += c[i];
        }
    }
}

// ---------------------------------------------------------------------------
// Kernel 4: bin edges into CSR, computing w per edge. 4 edges/thread.
// ---------------------------------------------------------------------------
__global__ __launch_bounds__(256)
void bin_kernel(const void* __restrict__ ei)
{
    int t = blockIdx.x * blockDim.x + threadIdx.x;
    if (t >= E_EDGES / 4) return;
    int4 s4, d4;
    if (g_idx32) {
        s4 = reinterpret_cast<const int4*>(ei)[t];
        d4 = reinterpret_cast<const int4*>(ei)[E_EDGES / 4 + t];
    } else {
        longlong2 p0 = reinterpret_cast<const longlong2*>(ei)[2 * t];
        longlong2 p1 = reinterpret_cast<const longlong2*>(ei)[2 * t + 1];
        longlong2 q0 = reinterpret_cast<const longlong2*>(ei)[E_EDGES / 2 + 2 * t];
        longlong2 q1 = reinterpret_cast<const longlong2*>(ei)[E_EDGES / 2 + 2 * t + 1];
        s4 = make_int4((int)p0.x, (int)p0.y, (int)p1.x, (int)p1.y);
        d4 = make_int4((int)q0.x, (int)q0.y, (int)q1.x, (int)q1.y);
    }
    int ss[4] = {s4.x, s4.y, s4.z, s4.w};
    int dd[4] = {d4.x, d4.y, d4.z, d4.w};
    #pragma unroll
    for (int i = 0; i < 4; i++) {
        float score = g_ssrc[ss[i]] + g_sdst[dd[i]];
        float lr = score > 0.f ? score : SLOPE * score;
        float w = __expf(lr);
        int pos = atomicAdd(&g_pos[ss[i]], 1);
        g_edge[pos] = make_int2(dd[i], __float_as_int(w));
    }
}

// ---------------------------------------------------------------------------
// Kernel 5: aggregate. One warp per node; 16 lanes per edge (float4 each),
// 2 edges in flight per warp, 8 edges per unrolled iteration, FFMA2 math.
// ---------------------------------------------------------------------------
__global__ __launch_bounds__(256)
void aggregate_kernel(float* __restrict__ out)
{
    const int warp = (blockIdx.x * blockDim.x + threadIdx.x) >> 5;
    const int lane = threadIdx.x & 31;
    if (warp >= N_NODES) return;

    const int sub = lane >> 4;      // which of 2 concurrent edges
    const int sl  = lane & 15;      // float4 slot within a row

    const int beg = g_off[warp];
    const int end = beg + g_cnt[warp];

    unsigned long long axy = 0, azw = 0;   // packed accumulators
    float rsum = 0.f;
    const ulonglong2* gn = reinterpret_cast<const ulonglong2*>(g_new);

    int j = beg + sub;
    for (; j + 6 < end; j += 8) {
        int2 e0 = g_edge[j + 0];
        int2 e1 = g_edge[j + 2];
        int2 e2 = g_edge[j + 4];
        int2 e3 = g_edge[j + 6];
        ulonglong2 v0 = gn[(size_t)e0.x * 16 + sl];
        ulonglong2 v1 = gn[(size_t)e1.x * 16 + sl];
        ulonglong2 v2 = gn[(size_t)e2.x * 16 + sl];
        ulonglong2 v3 = gn[(size_t)e3.x * 16 + sl];
        float w0 = __int_as_float(e0.y), w1 = __int_as_float(e1.y);
        float w2 = __int_as_float(e2.y), w3 = __int_as_float(e3.y);
        unsigned long long wd0 = pack2(w0, w0), wd1 = pack2(w1, w1);
        unsigned long long wd2 = pack2(w2, w2), wd3 = pack2(w3, w3);
        fma2(axy, wd0, v0.x); fma2(azw, wd0, v0.y);
        fma2(axy, wd1, v1.x); fma2(azw, wd1, v1.y);
        fma2(axy, wd2, v2.x); fma2(azw, wd2, v2.y);
        fma2(axy, wd3, v3.x); fma2(azw, wd3, v3.y);
        rsum += (w0 + w1) + (w2 + w3);
    }
    for (; j < end; j += 2) {
        int2 e0 = g_edge[j];
        ulonglong2 v0 = gn[(size_t)e0.x * 16 + sl];
        float w0 = __int_as_float(e0.y);
        unsigned long long wd0 = pack2(w0, w0);
        fma2(axy, wd0, v0.x); fma2(azw, wd0, v0.y);
        rsum += w0;
    }

    float2 vxy = unpack2(axy);
    float2 vzw = unpack2(azw);
    float4 acc = make_float4(vxy.x, vxy.y, vzw.x, vzw.y);

    // combine the two edge-substreams (lanes l <-> l+16 hold same columns)
    acc.x += __shfl_xor_sync(0xffffffffu, acc.x, 16);
    acc.y += __shfl_xor_sync(0xffffffffu, acc.y, 16);
    acc.z += __shfl_xor_sync(0xffffffffu, acc.z, 16);
    acc.w += __shfl_xor_sync(0xffffffffu, acc.w, 16);
    rsum  += __shfl_xor_sync(0xffffffffu, rsum, 16);

    if (sub == 0) {
        float inv = 1.0f / (rsum + EPS);
        reinterpret_cast<float4*>(out)[(size_t)warp * 16 + sl] =
            make_float4(acc.x * inv, acc.y * inv, acc.z * inv, acc.w * inv);
    }
}

extern "C" void kernel_launch(void* const* d_in, const int* in_sizes, int n_in,
                              void* d_out, int out_size)
{
    // Size-based dispatch (all element counts distinct) — immune to ordering.
    const float* x = 0; const void* ei = 0; const float* W = 0;
    const float* b = 0; const float* a = 0;
    for (int i = 0; i < n_in; i++) {
        switch (in_sizes[i]) {
            case N_NODES * IN_DIM:       x  = (const float*)d_in[i]; break; // 6.4M
            case 2 * E_EDGES:            ei = d_in[i];               break; // 3.2M
            case OUT_DIM * IN_DIM:       W  = (const float*)d_in[i]; break; // 8192
            case OUT_DIM:                b  = (const float*)d_in[i]; break; // 64
            case 2 * OUT_DIM:            a  = (const float*)d_in[i]; break; // 128
        }
    }
    float* out = (float*)d_out;

    probe_zero_kernel<<<(N_NODES + 255) / 256, 256>>>((const unsigned*)ei);
    gemm_attn_hist_kernel<<<(N_NODES + GEMM_ROWS - 1) / GEMM_ROWS, 128>>>(x, W, b, a, ei);
    scan_part_kernel<<<SCAN_BLOCKS, SCAN_THREADS>>>();
    scan_top_kernel<<<1, 32>>>();
    scan_write_kernel<<<SCAN_BLOCKS, SCAN_THREADS>>>();
    bin_kernel<<<(E_EDGES / 4 + 255) / 256, 256>>>(ei);
    aggregate_kernel<<<(N_NODES * 32 + 255) / 256, 256>>>(out);
}